// round 7
// baseline (speedup 1.0000x reference)
#include <cuda_runtime.h>
#include <cuda_bf16.h>

// LocalDynamicGraph edge features:
//   out[b,n,c,k]    = x[b, idx[b,n,k], c] - x[b,n,c]   for c in [0,64)
//   out[b,n,64+c,k] = x[b,n,c]                          for c in [0,64)
// B=8, N=16384, C=64, K=20. Output (B,N,128,20) fp32 = 1.342 GB, write-bound.
// R6: best structure = R2 (pure STG, occ 92.7%). Refinement: drop the
// idx-staging barrier — each thread loads its 10 row indices via uniform
// __ldg (L1 broadcast), leaving a single barrier per point.

#define BDIM    8
#define NPTS    16384
#define CH      64
#define KNB     20
#define OUTPP   (2 * CH * KNB)   // 2560 floats per point
#define THREADS 128
#define PAD     65

// Runtime flag: 1 if idx buffer is genuinely int64, 0 if it is int32.
__device__ int g_idx_is64;

__global__ void detect_idx_dtype_kernel(const long long* __restrict__ p) {
    // Genuine int64 indices all lie in [0, 16384). int32 data aliased as
    // int64 puts a random nonzero index in the high 32 bits of almost every
    // word. Probe 8 words; false-positive prob ~ 16384^-8.
    int is64 = 1;
    #pragma unroll
    for (int i = 0; i < 8; i++) {
        long long v = p[i];
        if (v < 0 || v >= NPTS) is64 = 0;
    }
    g_idx_is64 = is64;
}

__global__ __launch_bounds__(THREADS)
void edge_feature_kernel(const float* __restrict__ x,
                         const void* __restrict__ idx_raw,
                         float* __restrict__ out) {
    const int pt = blockIdx.x;            // 0 .. B*N-1
    const int b  = pt >> 14;              // N = 16384
    const int n  = pt & (NPTS - 1);
    const int t  = threadIdx.x;

    // Holds (nbr - center), pre-subtracted. Stride 65: conflict-free columns.
    __shared__ float s_nbr[KNB][PAD];

    const float* xb   = x + (size_t)b * NPTS * CH;
    const float* xrow = xb + (size_t)n * CH;

    // --- thread owns channel c and 10 consecutive k ---
    const int c    = t & (CH - 1);        // 0..63
    const int half = t >> 6;              // warps 0,1 -> k 0..9; 2,3 -> k 10..19
    const float ctr_c = __ldg(xrow + c);

    // --- row indices: uniform __ldg per half (L1 broadcast, no barrier) ---
    int rows[10];
    const size_t ibase = (size_t)pt * KNB + half * 10;
    if (g_idx_is64) {
        const long long* ip = (const long long*)idx_raw + ibase;
        #pragma unroll
        for (int i = 0; i < 10; i++) rows[i] = (int)__ldg(ip + i);
    } else {
        const int* ip = (const int*)idx_raw + ibase;
        #pragma unroll
        for (int i = 0; i < 10; i++) rows[i] = __ldg(ip + i);
    }

    // --- issue all gathers (MLP=10, 256B-coalesced per half-warp-group) ---
    float g[10];
    #pragma unroll
    for (int i = 0; i < 10; i++)
        g[i] = xb[(size_t)rows[i] * CH + c];

    float4* outp = (float4*)(out + (size_t)pt * OUTPP);

    // --- center-broadcast half: independent of gathers, hides LDG latency.
    // out floats [1280,2560): out[64+c2][k] = xrow[c2]; j4 in [320,640).
    #pragma unroll
    for (int i = 0; i < 3; i++) {
        const int j4 = 320 + t + i * THREADS;
        if (j4 < 640) {
            const float ctr = __ldg(xrow + (j4 / 5 - CH));   // L1-hit broadcast
            __stcs(&outp[j4], make_float4(ctr, ctr, ctr, ctr));
        }
    }

    // --- commit pre-subtracted edge values to smem ---
    #pragma unroll
    for (int i = 0; i < 10; i++)
        s_nbr[half * 10 + i][c] = g[i] - ctr_c;
    __syncthreads();

    // --- edge half: out[c2][k] = s_nbr[k][c2]; j4 in [0,320) ---
    #pragma unroll
    for (int i = 0; i < 3; i++) {
        const int j4 = t + i * THREADS;
        if (j4 < 320) {
            const int c2 = j4 / 5;
            const int kk = (j4 - c2 * 5) * 4;
            float4 v;
            v.x = s_nbr[kk + 0][c2];
            v.y = s_nbr[kk + 1][c2];
            v.z = s_nbr[kk + 2][c2];
            v.w = s_nbr[kk + 3][c2];
            __stcs(&outp[j4], v);
        }
    }
}

extern "C" void kernel_launch(void* const* d_in, const int* in_sizes, int n_in,
                              void* d_out, int out_size) {
    const float* x   = (const float*)d_in[0];
    const void*  idx = d_in[1];
    float*       out = (float*)d_out;

    detect_idx_dtype_kernel<<<1, 1>>>((const long long*)idx);
    edge_feature_kernel<<<BDIM * NPTS, THREADS>>>(x, idx, out);
}

// round 8
// speedup vs baseline: 1.1155x; 1.1155x over previous
#include <cuda_runtime.h>
#include <cuda_bf16.h>

// LocalDynamicGraph edge features:
//   out[b,n,c,k]    = x[b, idx[b,n,k], c] - x[b,n,c]   for c in [0,64)
//   out[b,n,64+c,k] = x[b,n,c]                          for c in [0,64)
// B=8, N=16384, C=64, K=20. Output (B,N,128,20) fp32 = 1.342 GB, write-bound.
// FINAL (= R2, best of 7 variants at 198.0us / DRAM 84.1% / occ 92.7%):
//  - cooperative vectorized idx staging (one barrier)
//  - fixed channel per thread; 10 consecutive-k gathers at MLP=10
//  - center-broadcast half stored while gathers are in flight
//  - pre-subtracted edge values -> padded smem -> coalesced float4 __stcs
// TMA-bulk-store variants (R3/R4/R5) and barrier-free idx loads (R6) all
// measured neutral-to-worse: the kernel is pinned at the ~6.7 TB/s HBM3e
// write ceiling (HBM GB/s x time == output bytes in every profile).

#define BDIM    8
#define NPTS    16384
#define CH      64
#define KNB     20
#define OUTPP   (2 * CH * KNB)   // 2560 floats per point
#define THREADS 128
#define PAD     65

// Runtime flag: 1 if idx buffer is genuinely int64, 0 if it is int32.
__device__ int g_idx_is64;

__global__ void detect_idx_dtype_kernel(const long long* __restrict__ p) {
    // Genuine int64 indices all lie in [0, 16384). int32 data aliased as
    // int64 puts a random nonzero index in the high 32 bits of almost every
    // word. Probe 8 words; false-positive prob ~ 16384^-8.
    int is64 = 1;
    #pragma unroll
    for (int i = 0; i < 8; i++) {
        long long v = p[i];
        if (v < 0 || v >= NPTS) is64 = 0;
    }
    g_idx_is64 = is64;
}

__global__ __launch_bounds__(THREADS)
void edge_feature_kernel(const float* __restrict__ x,
                         const void* __restrict__ idx_raw,
                         float* __restrict__ out) {
    const int pt = blockIdx.x;            // 0 .. B*N-1
    const int b  = pt >> 14;              // N = 16384
    const int n  = pt & (NPTS - 1);
    const int t  = threadIdx.x;

    // s_nbr holds (nbr - center), i.e. the edge half, pre-subtracted.
    __shared__ float s_nbr[KNB][PAD];
    __shared__ int   s_nidx[24];          // rows 0..9 at [0..9], 10..19 at [12..21]

    const float* xb   = x + (size_t)b * NPTS * CH;
    const float* xrow = xb + (size_t)n * CH;

    // --- stage neighbor indices (threads 0..19, warp 0) ---
    if (t < KNB) {
        long long v;
        if (g_idx_is64) v = ((const long long*)idx_raw)[(size_t)pt * KNB + t];
        else            v = (long long)((const int*)idx_raw)[(size_t)pt * KNB + t];
        s_nidx[t < 10 ? t : t + 2] = (int)v;   // 16B-aligned bases per half
    }
    __syncthreads();

    // --- per-thread gather assignment: fixed channel, 10 consecutive rows ---
    const int c    = t & (CH - 1);        // 0..63
    const int half = t >> 6;              // warps 0,1 -> rows 0..9; 2,3 -> 10..19
    const float ctr_c = __ldg(xrow + c);  // one center value per thread

    // 10 consecutive row indices via 3 vector LDS (broadcast within groups)
    const int base = half * 12;
    int4 ra = *(const int4*)&s_nidx[base];
    int4 rb = *(const int4*)&s_nidx[base + 4];
    int2 rc = *(const int2*)&s_nidx[base + 8];
    int rows[10] = {ra.x, ra.y, ra.z, ra.w, rb.x, rb.y, rb.z, rb.w, rc.x, rc.y};

    // --- issue all gathers (MLP=10, 256B-coalesced per instruction) ---
    float g[10];
    #pragma unroll
    for (int i = 0; i < 10; i++)
        g[i] = xb[(size_t)rows[i] * CH + c];

    float4* outp = (float4*)(out + (size_t)pt * OUTPP);

    // --- center-broadcast half: independent of gathers, hides LDG latency.
    // out[64+c2][k] = center[c2]; j4 in [320,640).
    #pragma unroll
    for (int i = 0; i < 3; i++) {
        const int j4 = 320 + t + i * THREADS;
        if (j4 < 640) {
            const float ctr = __ldg(xrow + (j4 / 5 - CH));   // L1-hit broadcast
            __stcs(&outp[j4], make_float4(ctr, ctr, ctr, ctr));
        }
    }

    // --- commit pre-subtracted edge values to smem ---
    #pragma unroll
    for (int i = 0; i < 10; i++)
        s_nbr[half * 10 + i][c] = g[i] - ctr_c;
    __syncthreads();

    // --- edge half: out[c2][k] = s_nbr[k][c2]; j4 in [0,320) ---
    #pragma unroll
    for (int i = 0; i < 3; i++) {
        const int j4 = t + i * THREADS;
        if (j4 < 320) {
            const int c2 = j4 / 5;
            const int kk = (j4 - c2 * 5) * 4;
            float4 v;
            v.x = s_nbr[kk + 0][c2];
            v.y = s_nbr[kk + 1][c2];
            v.z = s_nbr[kk + 2][c2];
            v.w = s_nbr[kk + 3][c2];
            __stcs(&outp[j4], v);
        }
    }
}

extern "C" void kernel_launch(void* const* d_in, const int* in_sizes, int n_in,
                              void* d_out, int out_size) {
    const float* x   = (const float*)d_in[0];
    const void*  idx = d_in[1];
    float*       out = (float*)d_out;

    detect_idx_dtype_kernel<<<1, 1>>>((const long long*)idx);
    edge_feature_kernel<<<BDIM * NPTS, THREADS>>>(x, idx, out);
}

// round 9
// speedup vs baseline: 1.1247x; 1.0083x over previous
#include <cuda_runtime.h>
#include <cuda_bf16.h>

// LocalDynamicGraph edge features:
//   out[b,n,c,k]    = x[b, idx[b,n,k], c] - x[b,n,c]   for c in [0,64)
//   out[b,n,64+c,k] = x[b,n,c]                          for c in [0,64)
// B=8, N=16384, C=64, K=20. Output (B,N,128,20) fp32 = 1.342 GB, write-bound.
// Structure = R2 (best of 8 variants: 198.0us / DRAM 84% / occ 93%):
//  - fixed channel per thread; 10 consecutive-k gathers at MLP=10
//  - center-broadcast half stored while gathers are in flight
//  - pre-subtracted edge values -> padded smem -> coalesced float4 __stcs
// R8: fold the idx-dtype (int64 vs int32) probe into warp 0 of the main
// kernel via __ballot_sync (no extra barrier), deleting the separate
// 1-thread detector launch from the captured graph.
// TMA-store variants (R3/R4/R5), barrier-free idx loads (R6): all worse.
// The kernel is pinned at the ~6.7 TB/s HBM3e write ceiling
// (HBM GB/s x time == output bytes in every profile).

#define BDIM    8
#define NPTS    16384
#define CH      64
#define KNB     20
#define OUTPP   (2 * CH * KNB)   // 2560 floats per point
#define THREADS 128
#define PAD     65

__global__ __launch_bounds__(THREADS)
void edge_feature_kernel(const float* __restrict__ x,
                         const void* __restrict__ idx_raw,
                         float* __restrict__ out) {
    const int pt = blockIdx.x;            // 0 .. B*N-1
    const int b  = pt >> 14;              // N = 16384
    const int n  = pt & (NPTS - 1);
    const int t  = threadIdx.x;

    // s_nbr holds (nbr - center), i.e. the edge half, pre-subtracted.
    __shared__ float s_nbr[KNB][PAD];
    __shared__ int   s_nidx[24];          // rows 0..9 at [0..9], 10..19 at [12..21]

    const float* xb   = x + (size_t)b * NPTS * CH;
    const float* xrow = xb + (size_t)n * CH;

    // --- warp 0: probe idx dtype, then stage neighbor indices -------------
    // Genuine int64 indices all lie in [0, 16384). int32 data aliased as
    // int64 puts a random nonzero index in the high 32 bits of almost every
    // 8-byte word. Probe the first 8 words (same 64B for every CTA -> L2
    // broadcast); false-positive prob ~ 16384^-8. Resolved via ballot inside
    // warp 0, so index staging needs no extra synchronization.
    if (t < 32) {
        long long pv = ((const long long*)idx_raw)[t & 7];
        unsigned bad = __ballot_sync(0xffffffffu, pv < 0 || pv >= NPTS);
        const int is64 = (bad == 0u);
        if (t < KNB) {
            long long v;
            if (is64) v = ((const long long*)idx_raw)[(size_t)pt * KNB + t];
            else      v = (long long)((const int*)idx_raw)[(size_t)pt * KNB + t];
            s_nidx[t < 10 ? t : t + 2] = (int)v;   // 16B-aligned bases per half
        }
    }
    __syncthreads();

    // --- per-thread gather assignment: fixed channel, 10 consecutive rows ---
    const int c    = t & (CH - 1);        // 0..63
    const int half = t >> 6;              // warps 0,1 -> rows 0..9; 2,3 -> 10..19
    const float ctr_c = __ldg(xrow + c);  // one center value per thread

    // 10 consecutive row indices via 3 vector LDS (broadcast within groups)
    const int base = half * 12;
    int4 ra = *(const int4*)&s_nidx[base];
    int4 rb = *(const int4*)&s_nidx[base + 4];
    int2 rc = *(const int2*)&s_nidx[base + 8];
    int rows[10] = {ra.x, ra.y, ra.z, ra.w, rb.x, rb.y, rb.z, rb.w, rc.x, rc.y};

    // --- issue all gathers (MLP=10, 256B-coalesced per instruction) ---
    float g[10];
    #pragma unroll
    for (int i = 0; i < 10; i++)
        g[i] = xb[(size_t)rows[i] * CH + c];

    float4* outp = (float4*)(out + (size_t)pt * OUTPP);

    // --- center-broadcast half: independent of gathers, hides LDG latency.
    // out[64+c2][k] = center[c2]; j4 in [320,640).
    #pragma unroll
    for (int i = 0; i < 3; i++) {
        const int j4 = 320 + t + i * THREADS;
        if (j4 < 640) {
            const float ctr = __ldg(xrow + (j4 / 5 - CH));   // L1-hit broadcast
            __stcs(&outp[j4], make_float4(ctr, ctr, ctr, ctr));
        }
    }

    // --- commit pre-subtracted edge values to smem ---
    #pragma unroll
    for (int i = 0; i < 10; i++)
        s_nbr[half * 10 + i][c] = g[i] - ctr_c;
    __syncthreads();

    // --- edge half: out[c2][k] = s_nbr[k][c2]; j4 in [0,320) ---
    #pragma unroll
    for (int i = 0; i < 3; i++) {
        const int j4 = t + i * THREADS;
        if (j4 < 320) {
            const int c2 = j4 / 5;
            const int kk = (j4 - c2 * 5) * 4;
            float4 v;
            v.x = s_nbr[kk + 0][c2];
            v.y = s_nbr[kk + 1][c2];
            v.z = s_nbr[kk + 2][c2];
            v.w = s_nbr[kk + 3][c2];
            __stcs(&outp[j4], v);
        }
    }
}

extern "C" void kernel_launch(void* const* d_in, const int* in_sizes, int n_in,
                              void* d_out, int out_size) {
    const float* x   = (const float*)d_in[0];
    const void*  idx = d_in[1];
    float*       out = (float*)d_out;

    edge_feature_kernel<<<BDIM * NPTS, THREADS>>>(x, idx, out);
}